// round 7
// baseline (speedup 1.0000x reference)
#include <cuda_runtime.h>
#include <cstdint>

// ---------------------------------------------------------------------------
// PoincareEmbeddings: out[b,l,:] = custom ? T[cm] : Rw[rm] + lin_b
// where T[k] = lin_w @ mobius_add(logmap0(fixed[k]), train[k]) + lin_b
//
// R7 = R6 (mobius fused into GEMM, fragment-permuted smem) + the restored
// end-of-MMA __syncthreads() that closes the double-buffer race R6 introduced.
// ---------------------------------------------------------------------------

constexpr int P_    = 300;
constexpr int PPAD  = 320;
constexpr int E_    = 256;
constexpr int Kc    = 20000;
constexpr int KP1   = Kc + 1;
constexpr int KROWS = 20096;     // 314 * 64
constexpr int VMAX  = 100000;

__device__ float g_T[(size_t)KROWS * E_];     // projected custom embeddings (+bias)
__device__ float g_Wp[(size_t)E_ * PPAD];     // lin_w, tf32, fragment-permuted
__device__ unsigned long long g_ptr[VMAX];    // per-vocab row pointer | custom flag

__device__ __forceinline__ float tf32_rna(float x) {
    float r;
    asm("cvt.rna.tf32.f32 %0, %1;" : "=f"(r) : "f"(x));
    return r;
}

// ---------------------------------------------------------------------------
// Prep A: lin_w -> g_Wp in fragment-permuted tf32 layout.
// Layout: ((t_k*32 + t_n)*32 + lane)*2 + slot; fragment (8n x 8k) tile with
// lane = (n%8)*4 + (k%4), slot = (k/4)%2  (b0 = B[g][tg], b1 = B[g][tg+4]).
// ---------------------------------------------------------------------------
__global__ void __launch_bounds__(256) k_wprep(const float* __restrict__ W) {
    int idx = blockIdx.x * 256 + threadIdx.x;      // one float each
    if (idx >= E_ * PPAD) return;
    int slot = idx & 1;
    int lane = (idx >> 1) & 31;
    int t_n  = (idx >> 6) & 31;
    int t_k  = idx >> 11;                          // 0..39
    int n = t_n * 8 + (lane >> 2);
    int k = t_k * 8 + (lane & 3) + slot * 4;
    g_Wp[idx] = (k < P_) ? tf32_rna(__ldg(W + (size_t)n * P_ + k)) : 0.f;
}

// ---------------------------------------------------------------------------
// Prep B: per-vocab fused row pointer (bit0 => custom row, bias already folded)
// ---------------------------------------------------------------------------
__global__ void __launch_bounds__(256) k_ptab(const int* __restrict__ v2c,
                                              const int* __restrict__ v2r,
                                              const float* __restrict__ Rw, int V) {
    int v = blockIdx.x * 256 + threadIdx.x;
    if (v >= V) return;
    int cm = __ldg(v2c + v);
    int rm = __ldg(v2r + v);
    unsigned long long p;
    if (cm) p = (unsigned long long)(g_T + (size_t)cm * E_) | 1ULL;
    else    p = (unsigned long long)(Rw  + (size_t)rm * E_);
    g_ptr[v] = p;
}

// ---------------------------------------------------------------------------
// Fused mobius + tf32 GEMM.
// Block: BM=64 rows x BN=256 cols (all of E), BK=32, 256 threads, 8 warps
// in 2x4, warp tile 32x64 (2 m-frags x 8 n-frags).
// Phase 1: per-row (alpha,beta) from fixed/train dot products.
// Phase 2: k-loop; A tile formed in regs->permuted smem; B via cp.async
// (already permuted in global); double-buffered both, with BOTH syncs.
// ---------------------------------------------------------------------------
constexpr int BK     = 32;
constexpr int NIT    = PPAD / BK;      // 10
constexpr int B_ST   = 256 * BK;       // 8192 floats per B stage
constexpr int A_ST   = 64 * BK;        // 2048 floats per A stage
constexpr int SMEMF  = 2 * B_ST + 2 * A_ST + 128;

__device__ __forceinline__ void cpa16(uint32_t dst, const float* src) {
    asm volatile("cp.async.cg.shared.global [%0], [%1], 16;" :: "r"(dst), "l"(src));
}

__global__ void __launch_bounds__(256) k_gemm_fused(const float* __restrict__ fixed_w,
                                                    const float* __restrict__ train_w,
                                                    const float* __restrict__ bias) {
    extern __shared__ float sm[];
    float* Bsm[2]  = { sm,            sm + B_ST };
    float* Asm[2]  = { sm + 2 * B_ST, sm + 2 * B_ST + A_ST };
    float* coef    = sm + 2 * B_ST + 2 * A_ST;    // [64][2] alpha,beta

    int tid  = threadIdx.x;
    int warp = tid >> 5;
    int lane = tid & 31;
    int wm = warp >> 2;                 // 0..1
    int wn = warp & 3;                  // 0..3
    int g  = lane >> 2;
    int tg = lane & 3;
    int rowBase = blockIdx.x * 64;

    // ---------------- Phase 1: per-row mobius coefficients ----------------
    {
        int row = tid >> 2;             // 0..63
        int sub = tid & 3;
        int gr  = rowBase + row;
        int rs  = (gr < KP1) ? gr : 0;  // clamp padding rows
        const float* f = fixed_w + (size_t)rs * P_;
        const float* t = train_w + (size_t)rs * P_;

        float sf2 = 0.f, sft = 0.f, st2 = 0.f;
        for (int p = sub * 4; p < P_; p += 16) {
            float4 fv = __ldg((const float4*)(f + p));
            float4 tv = __ldg((const float4*)(t + p));
            sf2 += fv.x*fv.x + fv.y*fv.y + fv.z*fv.z + fv.w*fv.w;
            sft += fv.x*tv.x + fv.y*tv.y + fv.z*tv.z + fv.w*tv.w;
            st2 += tv.x*tv.x + tv.y*tv.y + tv.z*tv.z + tv.w*tv.w;
        }
#pragma unroll
        for (int off = 1; off <= 2; off <<= 1) {
            sf2 += __shfl_xor_sync(0xFFFFFFFFu, sf2, off);
            sft += __shfl_xor_sync(0xFFFFFFFFu, sft, off);
            st2 += __shfl_xor_sync(0xFFFFFFFFu, st2, off);
        }
        if (sub == 0) {
            float norm  = sqrtf(sf2);
            float scale = (norm > 0.f) ? (atanhf(norm) / norm) : 1.0f;
            float x2 = scale * scale * sf2;
            float xy = scale * sft;
            float y2 = st2;
            float cu = 1.f + 2.f * xy + y2;
            float ct = 1.f - x2;
            float inv = 1.f / fmaxf(1.f + 2.f * xy + x2 * y2, 1e-15f);
            float alpha = cu * scale * inv;
            float beta  = ct * inv;
            if (gr >= KP1) { alpha = 0.f; beta = 0.f; }   // padding rows -> 0
            coef[row * 2]     = alpha;
            coef[row * 2 + 1] = beta;
        }
    }
    __syncthreads();

    // --------------- A-formation / B-copy helpers --------------------------
    int ar  = tid >> 2;                  // row 0..63
    int ac0 = (tid & 3) * 8;             // col group base within BK
    int gr  = rowBase + ar;
    int rs  = (gr < KP1) ? gr : 0;
    float alpha = coef[ar * 2];
    float beta  = coef[ar * 2 + 1];
    const float* frow = fixed_w + (size_t)rs * P_;
    const float* trow = train_w + (size_t)rs * P_;
    // permuted STS base for this thread's 8 elements
    int t_kp = tid & 3;                  // local k8-tile
    int t_m  = ar >> 4;
    int lbase = (ar & 7) * 4;
    int sbase = (ar >> 3) & 1;
    int abase = ((t_kp * 4 + t_m) * 32) * 4;   // float offset of tile

    auto load_ft = [&](int p0, float4& f0, float4& f1, float4& t0, float4& t1) {
        int c0 = p0 + ac0;
        f0 = make_float4(0.f,0.f,0.f,0.f); f1 = f0; t0 = f0; t1 = f0;
        if (c0 < P_)     { f0 = __ldg((const float4*)(frow + c0));
                           t0 = __ldg((const float4*)(trow + c0)); }
        if (c0 + 4 < P_) { f1 = __ldg((const float4*)(frow + c0 + 4));
                           t1 = __ldg((const float4*)(trow + c0 + 4)); }
    };
    auto sts_A = [&](float* dst, const float4& fv, const float4& tv, int j) {
        int slot = sbase + 2 * j;
        float v0 = tf32_rna(alpha * fv.x + beta * tv.x);
        float v1 = tf32_rna(alpha * fv.y + beta * tv.y);
        float v2 = tf32_rna(alpha * fv.z + beta * tv.z);
        float v3 = tf32_rna(alpha * fv.w + beta * tv.w);
        dst[abase + (lbase + 0) * 4 + slot] = v0;
        dst[abase + (lbase + 1) * 4 + slot] = v1;
        dst[abase + (lbase + 2) * 4 + slot] = v2;
        dst[abase + (lbase + 3) * 4 + slot] = v3;
    };
    auto load_B = [&](int s, int it) {
        const float* src = g_Wp + (size_t)it * B_ST;
#pragma unroll
        for (int j = 0; j < 8; j++) {
            int c = (tid + j * 256) * 4;
            cpa16((uint32_t)__cvta_generic_to_shared(Bsm[s] + c), src + c);
        }
    };

    float acc[2][8][4];
#pragma unroll
    for (int mi = 0; mi < 2; mi++)
#pragma unroll
        for (int ni = 0; ni < 8; ni++)
#pragma unroll
            for (int r = 0; r < 4; r++) acc[mi][ni][r] = 0.f;

    // prologue: A0 + B0
    {
        float4 f0, f1, t0, t1;
        load_ft(0, f0, f1, t0, t1);
        sts_A(Asm[0], f0, t0, 0);
        sts_A(Asm[0], f1, t1, 1);
        load_B(0, 0);
        asm volatile("cp.async.commit_group;");
    }

    for (int it = 0; it < NIT; it++) {
        int cur = it & 1;
        // NOTE: writing Bsm[cur^1] here is safe ONLY because the end-of-MMA
        // __syncthreads() below closed iteration it-1's reads of that buffer.
        if (it + 1 < NIT) load_B(cur ^ 1, it + 1);
        asm volatile("cp.async.commit_group;");
        asm volatile("cp.async.wait_group 1;");
        __syncthreads();   // A(it)/B(it) visible to all warps

        // prefetch ft for next iter (hidden behind MMAs)
        float4 f0, f1, t0, t1;
        if (it + 1 < NIT) load_ft((it + 1) * BK, f0, f1, t0, t1);

        const float* Ac = Asm[cur];
        const float* Bc = Bsm[cur];
#pragma unroll
        for (int kk = 0; kk < 4; kk++) {       // 4 k8-steps per BK
            uint32_t a[2][4];
#pragma unroll
            for (int mi = 0; mi < 2; mi++) {
                float4 av = *(const float4*)(Ac + ((kk * 4 + wm * 2 + mi) * 32 + lane) * 4);
                a[mi][0] = __float_as_uint(av.x);
                a[mi][1] = __float_as_uint(av.y);
                a[mi][2] = __float_as_uint(av.z);
                a[mi][3] = __float_as_uint(av.w);
            }
#pragma unroll
            for (int ni = 0; ni < 8; ni++) {
                float2 bv = *(const float2*)(Bc + ((kk * 32 + wn * 8 + ni) * 32 + lane) * 2);
                uint32_t b0 = __float_as_uint(bv.x);
                uint32_t b1 = __float_as_uint(bv.y);
#pragma unroll
                for (int mi = 0; mi < 2; mi++) {
                    asm volatile(
                        "mma.sync.aligned.m16n8k8.row.col.f32.tf32.tf32.f32 "
                        "{%0,%1,%2,%3}, {%4,%5,%6,%7}, {%8,%9}, {%0,%1,%2,%3};"
                        : "+f"(acc[mi][ni][0]), "+f"(acc[mi][ni][1]),
                          "+f"(acc[mi][ni][2]), "+f"(acc[mi][ni][3])
                        : "r"(a[mi][0]), "r"(a[mi][1]), "r"(a[mi][2]), "r"(a[mi][3]),
                          "r"(b0), "r"(b1));
                }
            }
        }

        // A(it+1) into the other buffer; its old readers (iter it-1) were
        // closed by the previous iteration's end-sync.
        if (it + 1 < NIT) {
            sts_A(Asm[cur ^ 1], f0, t0, 0);
            sts_A(Asm[cur ^ 1], f1, t1, 1);
        }
        // END-OF-MMA BARRIER (the R6 bug was dropping this): no warp may
        // proceed to iteration it+1's load_B/sts_A overwrites of Bsm[cur]/
        // Asm[cur] until every warp has finished reading them above.
        __syncthreads();
    }

    // epilogue: +bias, float2 stores
#pragma unroll
    for (int mi = 0; mi < 2; mi++) {
#pragma unroll
        for (int ni = 0; ni < 8; ni++) {
            int col = wn * 64 + ni * 8 + tg * 2;
            float bx = __ldg(bias + col), by = __ldg(bias + col + 1);
            int r0 = rowBase + wm * 32 + mi * 16 + g;
            *(float2*)(g_T + (size_t)r0 * E_ + col) =
                make_float2(acc[mi][ni][0] + bx, acc[mi][ni][1] + by);
            *(float2*)(g_T + (size_t)(r0 + 8) * E_ + col) =
                make_float2(acc[mi][ni][2] + bx, acc[mi][ni][3] + by);
        }
    }
}

// ---------------------------------------------------------------------------
// Gather: single pass (R4-proven). 1 warp = 1 token, 2 float4/lane, streaming
// stores keep the gather tables L2-resident.
// ---------------------------------------------------------------------------
__global__ void __launch_bounds__(256) k_gather(const int* __restrict__ x,
                                                const float* __restrict__ lin_b,
                                                float4* __restrict__ out,
                                                int ntok) {
    int gtid = blockIdx.x * 256 + threadIdx.x;
    int tok = gtid >> 5;
    int e4  = gtid & 31;
    if (tok >= ntok) return;

    int v = __ldg(x + tok);
    unsigned long long t = __ldg(g_ptr + v);
    float s = (t & 1ULL) ? 0.f : 1.f;         // regular rows need +lin_b
    const float4* src = (const float4*)(t & ~1ULL);

    float4 a0 = __ldg(src + e4);
    float4 a1 = __ldg(src + e4 + 32);
    float4 b0 = __ldg((const float4*)lin_b + e4);
    float4 b1 = __ldg((const float4*)lin_b + e4 + 32);

    float4* dst = out + (size_t)tok * 64;
    __stcs(dst + e4,      make_float4(a0.x + s * b0.x, a0.y + s * b0.y,
                                      a0.z + s * b0.z, a0.w + s * b0.w));
    __stcs(dst + e4 + 32, make_float4(a1.x + s * b1.x, a1.y + s * b1.y,
                                      a1.z + s * b1.z, a1.w + s * b1.w));
}

// ---------------------------------------------------------------------------
// Launch (single stream). Inputs: 0:x 1:custom_indices(unused) 2:v2c 3:v2r
//  4:custom_fixed_w 5:custom_train_w 6:regular_w 7:lin_w 8:lin_b
// ---------------------------------------------------------------------------
extern "C" void kernel_launch(void* const* d_in, const int* in_sizes, int n_in,
                              void* d_out, int out_size) {
    const int*   x    = (const int*)d_in[0];
    const int*   v2c  = (const int*)d_in[2];
    const int*   v2r  = (const int*)d_in[3];
    const float* fw   = (const float*)d_in[4];
    const float* tw   = (const float*)d_in[5];
    const float* Rw   = (const float*)d_in[6];
    const float* W    = (const float*)d_in[7];
    const float* bias = (const float*)d_in[8];
    float4* out = (float4*)d_out;

    int ntok = in_sizes[0];
    int V    = in_sizes[2];

    static bool init_done = false;
    if (!init_done) {
        cudaFuncSetAttribute(k_gemm_fused, cudaFuncAttributeMaxDynamicSharedMemorySize,
                             SMEMF * (int)sizeof(float));
        init_done = true;
    }

    k_wprep<<<(E_ * PPAD + 255) / 256, 256>>>(W);
    k_ptab<<<(V + 255) / 256, 256>>>(v2c, v2r, Rw, V);
    k_gemm_fused<<<KROWS / 64, 256, SMEMF * sizeof(float)>>>(fw, tw, bias);

    int gthreads = ntok * 32;
    k_gather<<<(gthreads + 255) / 256, 256>>>(x, bias, out, ntok);
}

// round 8
// speedup vs baseline: 1.1264x; 1.1264x over previous
#include <cuda_runtime.h>
#include <cstdint>

// ---------------------------------------------------------------------------
// PoincareEmbeddings: out[b,l,:] = custom ? T[cm] : Rw[rm] + lin_b
// where T[k] = lin_w @ mobius_add(logmap0(fixed[k]), train[k]) + lin_b
//
// R8: UNFUSED again (R7 fusion regressed the GEMM), but k_mobius now writes
// its output g_Mp directly in the MMA fragment-permuted layout, so k_gemm is
// a pure cp.async double-buffered tensor pipeline with vectorized fragment
// loads (no A-formation, no per-block reductions).
// ---------------------------------------------------------------------------

constexpr int P_    = 300;
constexpr int PPAD  = 320;
constexpr int E_    = 256;
constexpr int Kc    = 20000;
constexpr int KP1   = Kc + 1;
constexpr int KROWS = 20096;     // 314 * 64
constexpr int NBT   = KROWS / 64; // 314 row-tiles
constexpr int VMAX  = 100000;

// A-permuted layout: g_Mp[((bt*10 + it)*16 + tile)*128 + lane*4 + reg]
//   bt = 64-row tile, it = BK(32)-chunk 0..9, tile = kk(0..3)*4 + m16(0..3),
//   m16n8k8 A-fragment: lane = g*4+tg holds {A[g][tg], A[g+8][tg],
//   A[g][tg+4], A[g+8][tg+4]} of the (m16 x k8) tile.
__device__ float g_Mp[(size_t)KROWS * PPAD];
__device__ float g_T[(size_t)KROWS * E_];     // projected custom embeddings (+bias)
__device__ float g_Wp[(size_t)E_ * PPAD];     // lin_w, tf32, fragment-permuted
__device__ unsigned long long g_ptr[VMAX];    // per-vocab row pointer | custom flag

__device__ __forceinline__ float tf32_rna(float x) {
    float r;
    asm("cvt.rna.tf32.f32 %0, %1;" : "=f"(r) : "f"(x));
    return r;
}

// ---------------------------------------------------------------------------
// Prep A: lin_w -> g_Wp fragment-permuted tf32 (validated in R7).
// idx = ((t_k*32 + t_n)*32 + lane)*2 + slot; n = t_n*8 + lane/4,
// k = t_k*8 + lane%4 + slot*4.
// ---------------------------------------------------------------------------
__global__ void __launch_bounds__(256) k_wprep(const float* __restrict__ W) {
    int idx = blockIdx.x * 256 + threadIdx.x;
    if (idx >= E_ * PPAD) return;
    int slot = idx & 1;
    int lane = (idx >> 1) & 31;
    int t_n  = (idx >> 6) & 31;
    int t_k  = idx >> 11;
    int n = t_n * 8 + (lane >> 2);
    int k = t_k * 8 + (lane & 3) + slot * 4;
    g_Wp[idx] = (k < P_) ? tf32_rna(__ldg(W + (size_t)n * P_ + k)) : 0.f;
}

// ---------------------------------------------------------------------------
// Prep B: per-vocab fused row pointer (bit0 => custom row)
// ---------------------------------------------------------------------------
__global__ void __launch_bounds__(256) k_ptab(const int* __restrict__ v2c,
                                              const int* __restrict__ v2r,
                                              const float* __restrict__ Rw, int V) {
    int v = blockIdx.x * 256 + threadIdx.x;
    if (v >= V) return;
    int cm = __ldg(v2c + v);
    int rm = __ldg(v2r + v);
    unsigned long long p;
    if (cm) p = (unsigned long long)(g_T + (size_t)cm * E_) | 1ULL;
    else    p = (unsigned long long)(Rw  + (size_t)rm * E_);
    g_ptr[v] = p;
}

// ---------------------------------------------------------------------------
// Kernel 1: mobius -> fragment-permuted A.
// 256 threads per block, 64 rows per block (matches one GEMM row-tile).
// Phase A: per-row (alpha,beta) via 4-thread dot products.
// Phase B: per 32-col chunk: compute vals into smem stage, emit permuted
// 8KB chunk with coalesced STG.128.
// ---------------------------------------------------------------------------
__global__ void __launch_bounds__(256) k_mobius(const float* __restrict__ fixed_w,
                                                const float* __restrict__ train_w) {
    __shared__ float coef[64][2];
    __shared__ float stage[64][36];   // stride 36 => conflict-free permuted reads

    int tid = threadIdx.x;
    int bt  = blockIdx.x;
    int row = tid >> 2;               // 0..63
    int sub = tid & 3;
    int gr  = bt * 64 + row;
    int rs  = (gr < KP1) ? gr : 0;
    const float* frow = fixed_w + (size_t)rs * P_;
    const float* trow = train_w + (size_t)rs * P_;

    // ---- Phase A: coefficients ----
    {
        float sf2 = 0.f, sft = 0.f, st2 = 0.f;
        for (int p = sub * 4; p < P_; p += 16) {
            float4 fv = __ldg((const float4*)(frow + p));
            float4 tv = __ldg((const float4*)(trow + p));
            sf2 += fv.x*fv.x + fv.y*fv.y + fv.z*fv.z + fv.w*fv.w;
            sft += fv.x*tv.x + fv.y*tv.y + fv.z*tv.z + fv.w*tv.w;
            st2 += tv.x*tv.x + tv.y*tv.y + tv.z*tv.z + tv.w*tv.w;
        }
#pragma unroll
        for (int off = 1; off <= 2; off <<= 1) {
            sf2 += __shfl_xor_sync(0xFFFFFFFFu, sf2, off);
            sft += __shfl_xor_sync(0xFFFFFFFFu, sft, off);
            st2 += __shfl_xor_sync(0xFFFFFFFFu, st2, off);
        }
        if (sub == 0) {
            float norm  = sqrtf(sf2);
            float scale = (norm > 0.f) ? (atanhf(norm) / norm) : 1.0f;
            float x2 = scale * scale * sf2;
            float xy = scale * sft;
            float y2 = st2;
            float cu = 1.f + 2.f * xy + y2;
            float ct = 1.f - x2;
            float inv = 1.f / fmaxf(1.f + 2.f * xy + x2 * y2, 1e-15f);
            float alpha = cu * scale * inv;
            float beta  = ct * inv;
            if (gr >= KP1) { alpha = 0.f; beta = 0.f; }
            coef[row][0] = alpha;
            coef[row][1] = beta;
        }
    }
    __syncthreads();

    float alpha = coef[row][0];
    float beta  = coef[row][1];
    int c8 = sub * 8;                                 // col base within chunk

    for (int it = 0; it < PPAD / 32; it++) {
        int p0 = it * 32 + c8;
        float4 f0 = make_float4(0.f,0.f,0.f,0.f), f1 = f0, t0 = f0, t1 = f0;
        if (p0 < P_)     { f0 = __ldg((const float4*)(frow + p0));
                           t0 = __ldg((const float4*)(trow + p0)); }
        if (p0 + 4 < P_) { f1 = __ldg((const float4*)(frow + p0 + 4));
                           t1 = __ldg((const float4*)(trow + p0 + 4)); }
        stage[row][c8 + 0] = tf32_rna(alpha * f0.x + beta * t0.x);
        stage[row][c8 + 1] = tf32_rna(alpha * f0.y + beta * t0.y);
        stage[row][c8 + 2] = tf32_rna(alpha * f0.z + beta * t0.z);
        stage[row][c8 + 3] = tf32_rna(alpha * f0.w + beta * t0.w);
        stage[row][c8 + 4] = tf32_rna(alpha * f1.x + beta * t1.x);
        stage[row][c8 + 5] = tf32_rna(alpha * f1.y + beta * t1.y);
        stage[row][c8 + 6] = tf32_rna(alpha * f1.z + beta * t1.z);
        stage[row][c8 + 7] = tf32_rna(alpha * f1.w + beta * t1.w);
        __syncthreads();

        // emit permuted chunk: 512 float4, 2 per thread, coalesced
        float4* dst = (float4*)(g_Mp + ((size_t)bt * 10 + it) * 2048);
#pragma unroll
        for (int h = 0; h < 2; h++) {
            int q    = tid + h * 256;        // 0..511
            int tile = q >> 5;               // kk*4 + m16
            int lane = q & 31;
            int kk   = tile >> 2;
            int tm   = tile & 3;
            int g    = lane >> 2;
            int tg   = lane & 3;
            int r0 = tm * 16 + g;
            int k0 = kk * 8 + tg;
            dst[q] = make_float4(stage[r0][k0],     stage[r0 + 8][k0],
                                 stage[r0][k0 + 4], stage[r0 + 8][k0 + 4]);
        }
        __syncthreads();   // stage reused next chunk
    }
}

// ---------------------------------------------------------------------------
// Kernel 2: pure tf32 MMA GEMM on permuted operands.
// Block: 64 rows x 256 cols (all E), BK=32, 8 warps (2x4), warp 32x64.
// 2-stage cp.async double buffer for A (8KB) and B (32KB).
// ---------------------------------------------------------------------------
constexpr int BK    = 32;
constexpr int NIT   = PPAD / BK;      // 10
constexpr int A_ST  = 2048;           // floats per A stage
constexpr int B_ST  = 8192;           // floats per B stage
constexpr int SMEMF = 2 * (A_ST + B_ST);

__device__ __forceinline__ void cpa16(uint32_t dst, const float* src) {
    asm volatile("cp.async.cg.shared.global [%0], [%1], 16;" :: "r"(dst), "l"(src));
}

__global__ void __launch_bounds__(256) k_gemm(const float* __restrict__ bias) {
    extern __shared__ float sm[];
    float* Bsm[2] = { sm,            sm + B_ST };
    float* Asm[2] = { sm + 2 * B_ST, sm + 2 * B_ST + A_ST };

    int tid  = threadIdx.x;
    int warp = tid >> 5;
    int lane = tid & 31;
    int wm = warp >> 2;                 // 0..1
    int wn = warp & 3;                  // 0..3
    int g  = lane >> 2;
    int tg = lane & 3;
    int bt = blockIdx.x;
    int rowBase = bt * 64;

    auto load_stage = [&](int s, int it) {
        const float* Bsrc = g_Wp + (size_t)it * B_ST;
#pragma unroll
        for (int j = 0; j < 8; j++) {
            int c = (tid + j * 256) * 4;
            cpa16((uint32_t)__cvta_generic_to_shared(Bsm[s] + c), Bsrc + c);
        }
        const float* Asrc = g_Mp + ((size_t)bt * NIT + it) * A_ST;
#pragma unroll
        for (int j = 0; j < 2; j++) {
            int c = (tid + j * 256) * 4;
            cpa16((uint32_t)__cvta_generic_to_shared(Asm[s] + c), Asrc + c);
        }
    };

    float acc[2][8][4];
#pragma unroll
    for (int mi = 0; mi < 2; mi++)
#pragma unroll
        for (int ni = 0; ni < 8; ni++)
#pragma unroll
            for (int r = 0; r < 4; r++) acc[mi][ni][r] = 0.f;

    load_stage(0, 0);
    asm volatile("cp.async.commit_group;");

    for (int it = 0; it < NIT; it++) {
        int cur = it & 1;
        if (it + 1 < NIT) load_stage(cur ^ 1, it + 1);
        asm volatile("cp.async.commit_group;");
        asm volatile("cp.async.wait_group 1;");
        __syncthreads();                      // stage(it) ready for all warps

        const float* Ac = Asm[cur];
        const float* Bc = Bsm[cur];
#pragma unroll
        for (int kk = 0; kk < 4; kk++) {
            uint32_t a[2][4];
#pragma unroll
            for (int mi = 0; mi < 2; mi++) {
                float4 av = *(const float4*)(Ac + ((kk * 4 + wm * 2 + mi) * 32 + lane) * 4);
                a[mi][0] = __float_as_uint(av.x);
                a[mi][1] = __float_as_uint(av.y);
                a[mi][2] = __float_as_uint(av.z);
                a[mi][3] = __float_as_uint(av.w);
            }
#pragma unroll
            for (int ni = 0; ni < 8; ni++) {
                float2 bv = *(const float2*)(Bc + ((kk * 32 + wn * 8 + ni) * 32 + lane) * 2);
                uint32_t b0 = __float_as_uint(bv.x);
                uint32_t b1 = __float_as_uint(bv.y);
#pragma unroll
                for (int mi = 0; mi < 2; mi++) {
                    asm volatile(
                        "mma.sync.aligned.m16n8k8.row.col.f32.tf32.tf32.f32 "
                        "{%0,%1,%2,%3}, {%4,%5,%6,%7}, {%8,%9}, {%0,%1,%2,%3};"
                        : "+f"(acc[mi][ni][0]), "+f"(acc[mi][ni][1]),
                          "+f"(acc[mi][ni][2]), "+f"(acc[mi][ni][3])
                        : "r"(a[mi][0]), "r"(a[mi][1]), "r"(a[mi][2]), "r"(a[mi][3]),
                          "r"(b0), "r"(b1));
                }
            }
        }
        __syncthreads();   // close readers before next iteration's overwrites
    }

    // epilogue: +bias, float2 stores (layout validated in R7)
#pragma unroll
    for (int mi = 0; mi < 2; mi++) {
#pragma unroll
        for (int ni = 0; ni < 8; ni++) {
            int col = wn * 64 + ni * 8 + tg * 2;
            float bx = __ldg(bias + col), by = __ldg(bias + col + 1);
            int r0 = rowBase + wm * 32 + mi * 16 + g;
            *(float2*)(g_T + (size_t)r0 * E_ + col) =
                make_float2(acc[mi][ni][0] + bx, acc[mi][ni][1] + by);
            *(float2*)(g_T + (size_t)(r0 + 8) * E_ + col) =
                make_float2(acc[mi][ni][2] + bx, acc[mi][ni][3] + by);
        }
    }
}

// ---------------------------------------------------------------------------
// Kernel 3: gather (R4/R7-proven, at its traffic roofline).
// ---------------------------------------------------------------------------
__global__ void __launch_bounds__(256) k_gather(const int* __restrict__ x,
                                                const float* __restrict__ lin_b,
                                                float4* __restrict__ out,
                                                int ntok) {
    int gtid = blockIdx.x * 256 + threadIdx.x;
    int tok = gtid >> 5;
    int e4  = gtid & 31;
    if (tok >= ntok) return;

    int v = __ldg(x + tok);
    unsigned long long t = __ldg(g_ptr + v);
    float s = (t & 1ULL) ? 0.f : 1.f;
    const float4* src = (const float4*)(t & ~1ULL);

    float4 a0 = __ldg(src + e4);
    float4 a1 = __ldg(src + e4 + 32);
    float4 b0 = __ldg((const float4*)lin_b + e4);
    float4 b1 = __ldg((const float4*)lin_b + e4 + 32);

    float4* dst = out + (size_t)tok * 64;
    __stcs(dst + e4,      make_float4(a0.x + s * b0.x, a0.y + s * b0.y,
                                      a0.z + s * b0.z, a0.w + s * b0.w));
    __stcs(dst + e4 + 32, make_float4(a1.x + s * b1.x, a1.y + s * b1.y,
                                      a1.z + s * b1.z, a1.w + s * b1.w));
}

// ---------------------------------------------------------------------------
// Launch. Inputs: 0:x 1:custom_indices(unused) 2:v2c 3:v2r
//  4:custom_fixed_w 5:custom_train_w 6:regular_w 7:lin_w 8:lin_b
// ---------------------------------------------------------------------------
extern "C" void kernel_launch(void* const* d_in, const int* in_sizes, int n_in,
                              void* d_out, int out_size) {
    const int*   x    = (const int*)d_in[0];
    const int*   v2c  = (const int*)d_in[2];
    const int*   v2r  = (const int*)d_in[3];
    const float* fw   = (const float*)d_in[4];
    const float* tw   = (const float*)d_in[5];
    const float* Rw   = (const float*)d_in[6];
    const float* W    = (const float*)d_in[7];
    const float* bias = (const float*)d_in[8];
    float4* out = (float4*)d_out;

    int ntok = in_sizes[0];
    int V    = in_sizes[2];

    static bool init_done = false;
    if (!init_done) {
        cudaFuncSetAttribute(k_gemm, cudaFuncAttributeMaxDynamicSharedMemorySize,
                             SMEMF * (int)sizeof(float));
        init_done = true;
    }

    k_wprep<<<(E_ * PPAD + 255) / 256, 256>>>(W);
    k_ptab<<<(V + 255) / 256, 256>>>(v2c, v2r, Rw, V);
    k_mobius<<<NBT, 256>>>(fw, tw);
    k_gemm<<<NBT, 256, SMEMF * sizeof(float)>>>(bias);

    int gthreads = ntok * 32;
    k_gather<<<(gthreads + 255) / 256, 256>>>(x, bias, out, ntok);
}